// round 1
// baseline (speedup 1.0000x reference)
#include <cuda_runtime.h>
#include <math.h>

#define B_ 8
#define N_ 1024
#define E_ 768
#define H_ 12
#define D_ 64
#define M_ (B_*N_)   // 8192

// Scratch (no allocations allowed)
__device__ float g_qkv[(size_t)M_ * 3 * E_];      // [M, 2304]
__device__ float g_q[(size_t)B_*H_*N_*D_];        // [B,H,N,D]
__device__ float g_k[(size_t)B_*H_*N_*D_];
__device__ float g_v[(size_t)B_*H_*N_*D_];
__device__ float g_ao[(size_t)M_ * E_];           // attention out, [B,N,E] = [M,768]

// ---------------------------------------------------------------------------
// Generic SGEMM: C[M,N] = A[M,K] @ B[K,N] + bias[N]
// BM=128, BN=64, BK=8, 256 threads, 8x4 per thread.
// ---------------------------------------------------------------------------
__global__ __launch_bounds__(256) void sgemm_bias(
    const float* __restrict__ A, const float* __restrict__ Bm,
    const float* __restrict__ bias, float* __restrict__ C,
    int M, int N, int K)
{
    __shared__ float As[8][128];   // [k][m] (transposed)
    __shared__ float Bs[8][64];    // [k][n]

    int tid = threadIdx.x;
    int m0 = blockIdx.y * 128;
    int n0 = blockIdx.x * 64;
    int ty = tid >> 4;          // 0..15, 8 rows each
    int tx = tid & 15;          // 0..15, 4 cols each

    int arow = tid >> 1;               // 0..127
    int acol = (tid & 1) * 4;          // 0 or 4
    int brow = tid >> 5;               // 0..7
    int bcol = (tid & 31) * 2;         // 0..62

    float acc[8][4];
    #pragma unroll
    for (int i = 0; i < 8; i++)
        #pragma unroll
        for (int j = 0; j < 4; j++) acc[i][j] = 0.f;

    for (int kb = 0; kb < K; kb += 8) {
        float4 av = *(const float4*)&A[(size_t)(m0 + arow) * K + kb + acol];
        As[acol + 0][arow] = av.x;
        As[acol + 1][arow] = av.y;
        As[acol + 2][arow] = av.z;
        As[acol + 3][arow] = av.w;
        float2 bv = *(const float2*)&Bm[(size_t)(kb + brow) * N + n0 + bcol];
        Bs[brow][bcol]     = bv.x;
        Bs[brow][bcol + 1] = bv.y;
        __syncthreads();

        #pragma unroll
        for (int kk = 0; kk < 8; kk++) {
            float4 a0 = *(float4*)&As[kk][ty * 8];
            float4 a1 = *(float4*)&As[kk][ty * 8 + 4];
            float4 b  = *(float4*)&Bs[kk][tx * 4];
            float am[8] = {a0.x, a0.y, a0.z, a0.w, a1.x, a1.y, a1.z, a1.w};
            float bn[4] = {b.x, b.y, b.z, b.w};
            #pragma unroll
            for (int i = 0; i < 8; i++)
                #pragma unroll
                for (int j = 0; j < 4; j++)
                    acc[i][j] += am[i] * bn[j];
        }
        __syncthreads();
    }

    float4 bv = *(const float4*)&bias[n0 + tx * 4];
    #pragma unroll
    for (int i = 0; i < 8; i++) {
        float4 o;
        o.x = acc[i][0] + bv.x;
        o.y = acc[i][1] + bv.y;
        o.z = acc[i][2] + bv.z;
        o.w = acc[i][3] + bv.w;
        *(float4*)&C[(size_t)(m0 + ty * 8 + i) * N + n0 + tx * 4] = o;
    }
}

// ---------------------------------------------------------------------------
// RoPE + split: g_qkv [B,N,3,H,D] -> g_q/g_k (roped), g_v, each [B,H,N,D].
// RoPE here rotates by angle f(h, d) -- constant along the sequence axis.
// One thread per (b,h,t,d2), d2 in [0,32) handles the (d2, d2+32) pair.
// ---------------------------------------------------------------------------
__global__ void rope_split(const float* __restrict__ qkv,
                           float* __restrict__ Qo, float* __restrict__ Ko,
                           float* __restrict__ Vo)
{
    int idx = blockIdx.x * blockDim.x + threadIdx.x;
    const int total = B_ * H_ * N_ * 32;
    if (idx >= total) return;
    int d2 = idx & 31;
    int rest = idx >> 5;
    int t = rest & (N_ - 1);
    int rest2 = rest >> 10;
    int h = rest2 % H_;
    int b = rest2 / H_;

    // inv_freq[d2] = 10000^(-d2/32); freq = h * inv_freq
    float f = (float)h * exp2f(-(float)d2 * (13.287712379549449f / 32.0f));
    float s, c;
    sincosf(f, &s, &c);

    const float* base = qkv + ((size_t)(b * N_ + t)) * (3 * E_) + h * D_;
    float q1 = base[d2],        q2 = base[d2 + 32];
    float k1 = base[E_ + d2],   k2 = base[E_ + d2 + 32];
    float v1 = base[2*E_ + d2], v2 = base[2*E_ + d2 + 32];

    size_t ob = ((size_t)((b * H_ + h) * N_ + t)) * D_;
    Qo[ob + d2]      = q1 * c - q2 * s;
    Qo[ob + d2 + 32] = q2 * c + q1 * s;
    Ko[ob + d2]      = k1 * c - k2 * s;
    Ko[ob + d2 + 32] = k2 * c + k1 * s;
    Vo[ob + d2]      = v1;
    Vo[ob + d2 + 32] = v2;
}

// ---------------------------------------------------------------------------
// Flash attention, fp32. Each block: one (b,h), 64 query rows.
// 256 threads; thread (ty,tx) owns rows ty*4..+3, cols tx*4..+3 of each
// 64x64 S tile and of the 64x64 O accumulator (cols = head dims).
// ---------------------------------------------------------------------------
#define SM_STRIDE 68
__global__ __launch_bounds__(256) void attn_kernel(
    const float* __restrict__ Q, const float* __restrict__ K,
    const float* __restrict__ V, float* __restrict__ O)
{
    extern __shared__ float sm[];
    float* QsT = sm;                        // [d][r]  64 x 68
    float* KsT = sm + 64 * SM_STRIDE;       // [d][c]
    float* Vs  = sm + 2 * 64 * SM_STRIDE;   // [j][d]
    float* PsT = sm + 3 * 64 * SM_STRIDE;   // [j][r]

    int tid = threadIdx.x;
    int bh = blockIdx.y;
    int b = bh / H_, h = bh % H_;
    int q0 = blockIdx.x * 64;
    const float* Qb = Q + (size_t)bh * N_ * D_;
    const float* Kb = K + (size_t)bh * N_ * D_;
    const float* Vb = V + (size_t)bh * N_ * D_;

    const float scale = 0.125f;  // 64^-0.5
    for (int idx = tid; idx < 64 * 64; idx += 256) {
        int r = idx >> 6, d = idx & 63;
        QsT[d * SM_STRIDE + r] = Qb[(size_t)(q0 + r) * D_ + d] * scale;
    }

    int ty = tid >> 4, tx = tid & 15;
    int r0 = ty * 4, c0 = tx * 4;

    float o[4][4];
    #pragma unroll
    for (int i = 0; i < 4; i++)
        #pragma unroll
        for (int j = 0; j < 4; j++) o[i][j] = 0.f;
    float mrow[4] = {-1e30f, -1e30f, -1e30f, -1e30f};
    float lrow[4] = {0.f, 0.f, 0.f, 0.f};

    for (int jt = 0; jt < N_; jt += 64) {
        __syncthreads();  // previous PV done before overwriting K/V tiles
        for (int idx = tid; idx < 64 * 64; idx += 256) {
            int r = idx >> 6, d = idx & 63;
            float kv = Kb[(size_t)(jt + r) * D_ + d];
            float vv = Vb[(size_t)(jt + r) * D_ + d];
            KsT[d * SM_STRIDE + r] = kv;
            Vs[r * SM_STRIDE + d]  = vv;
        }
        __syncthreads();

        // S = (Q*scale) @ K^T : contraction over d
        float s[4][4];
        #pragma unroll
        for (int i = 0; i < 4; i++)
            #pragma unroll
            for (int j = 0; j < 4; j++) s[i][j] = 0.f;
        #pragma unroll 8
        for (int k = 0; k < 64; k++) {
            float4 qa = *(float4*)&QsT[k * SM_STRIDE + r0];
            float4 kb = *(float4*)&KsT[k * SM_STRIDE + c0];
            float qq[4] = {qa.x, qa.y, qa.z, qa.w};
            float kk[4] = {kb.x, kb.y, kb.z, kb.w};
            #pragma unroll
            for (int i = 0; i < 4; i++)
                #pragma unroll
                for (int j = 0; j < 4; j++)
                    s[i][j] += qq[i] * kk[j];
        }

        // online softmax update
        float fac[4];
        #pragma unroll
        for (int i = 0; i < 4; i++) {
            float mt = fmaxf(fmaxf(s[i][0], s[i][1]), fmaxf(s[i][2], s[i][3]));
            #pragma unroll
            for (int off = 8; off; off >>= 1)
                mt = fmaxf(mt, __shfl_xor_sync(0xffffffffu, mt, off));
            float mnew = fmaxf(mrow[i], mt);
            fac[i] = __expf(mrow[i] - mnew);
            mrow[i] = mnew;
            float ps = 0.f;
            #pragma unroll
            for (int j = 0; j < 4; j++) {
                float p = __expf(s[i][j] - mnew);
                s[i][j] = p;
                ps += p;
            }
            #pragma unroll
            for (int off = 8; off; off >>= 1)
                ps += __shfl_xor_sync(0xffffffffu, ps, off);
            lrow[i] = lrow[i] * fac[i] + ps;
            #pragma unroll
            for (int j = 0; j < 4; j++) o[i][j] *= fac[i];
        }

        // stage P^T to smem: PsT[col][row]
        #pragma unroll
        for (int j = 0; j < 4; j++) {
            float4 pv = {s[0][j], s[1][j], s[2][j], s[3][j]};
            *(float4*)&PsT[(c0 + j) * SM_STRIDE + r0] = pv;
        }
        __syncthreads();

        // O += P @ V : contraction over j (keys)
        #pragma unroll 8
        for (int j = 0; j < 64; j++) {
            float4 pa = *(float4*)&PsT[j * SM_STRIDE + r0];
            float4 vb = *(float4*)&Vs[j * SM_STRIDE + c0];
            float pp[4] = {pa.x, pa.y, pa.z, pa.w};
            float vv[4] = {vb.x, vb.y, vb.z, vb.w};
            #pragma unroll
            for (int i = 0; i < 4; i++)
                #pragma unroll
                for (int jj = 0; jj < 4; jj++)
                    o[i][jj] += pp[i] * vv[jj];
        }
    }

    // epilogue: normalize, write to [B, N, H*D]
    #pragma unroll
    for (int i = 0; i < 4; i++) {
        float inv = 1.0f / lrow[i];
        int row = q0 + r0 + i;
        float4 ov = {o[i][0] * inv, o[i][1] * inv, o[i][2] * inv, o[i][3] * inv};
        *(float4*)&O[(size_t)(b * N_ + row) * E_ + h * D_ + c0] = ov;
    }
}

// ---------------------------------------------------------------------------
extern "C" void kernel_launch(void* const* d_in, const int* in_sizes, int n_in,
                              void* d_out, int out_size)
{
    (void)in_sizes; (void)n_in; (void)out_size;
    const float* x      = (const float*)d_in[0];
    const float* w_qkv  = (const float*)d_in[1];
    const float* b_qkv  = (const float*)d_in[2];
    const float* w_proj = (const float*)d_in[3];
    const float* b_proj = (const float*)d_in[4];
    float* out = (float*)d_out;

    float *qkv, *q, *k, *v, *ao;
    cudaGetSymbolAddress((void**)&qkv, g_qkv);
    cudaGetSymbolAddress((void**)&q,   g_q);
    cudaGetSymbolAddress((void**)&k,   g_k);
    cudaGetSymbolAddress((void**)&v,   g_v);
    cudaGetSymbolAddress((void**)&ao,  g_ao);

    // 1) QKV GEMM: [8192,768] @ [768,2304] + bias
    {
        dim3 grid(3 * E_ / 64, M_ / 128);
        sgemm_bias<<<grid, 256>>>(x, w_qkv, b_qkv, qkv, M_, 3 * E_, E_);
    }

    // 2) RoPE + split into [B,H,N,D]
    {
        int total = B_ * H_ * N_ * 32;
        rope_split<<<(total + 255) / 256, 256>>>(qkv, q, k, v);
    }

    // 3) Attention
    {
        static bool attr_set = false;
        size_t smem = 4 * 64 * SM_STRIDE * sizeof(float);  // 69632 B
        cudaFuncSetAttribute(attn_kernel, cudaFuncAttributeMaxDynamicSharedMemorySize,
                             (int)smem);
        dim3 grid(N_ / 64, B_ * H_);
        attn_kernel<<<grid, 256, smem>>>(q, k, v, ao);
        (void)attr_set;
    }

    // 4) Output projection: [8192,768] @ [768,768] + bias
    {
        dim3 grid(E_ / 64, M_ / 128);
        sgemm_bias<<<grid, 256>>>(ao, w_proj, b_proj, out, M_, E_, E_);
    }
}

// round 3
// speedup vs baseline: 1.4593x; 1.4593x over previous
#include <cuda_runtime.h>
#include <cuda_bf16.h>
#include <math.h>
#include <stdint.h>

#define B_ 8
#define N_ 1024
#define E_ 768
#define H_ 12
#define D_ 64
#define M_ (B_*N_)   // 8192

// ---------------------------------------------------------------------------
// Scratch (__device__ globals; no allocations allowed)
// ---------------------------------------------------------------------------
__device__ float g_qkv[(size_t)M_ * 3 * E_];          // [M, 2304]
__device__ float g_q[(size_t)B_*H_*N_*D_];
__device__ float g_k[(size_t)B_*H_*N_*D_];
__device__ float g_v[(size_t)B_*H_*N_*D_];
__device__ float g_ao[(size_t)M_ * E_];               // attention out [M,768]
__device__ __nv_bfloat16 g_xh[(size_t)M_ * E_];       // x split
__device__ __nv_bfloat16 g_xl[(size_t)M_ * E_];
__device__ __nv_bfloat16 g_wqh[(size_t)3*E_ * E_];    // w_qkv^T split [2304,768]
__device__ __nv_bfloat16 g_wql[(size_t)3*E_ * E_];
__device__ __nv_bfloat16 g_wph[(size_t)E_ * E_];      // w_proj^T split [768,768]
__device__ __nv_bfloat16 g_wpl[(size_t)E_ * E_];
__device__ __nv_bfloat16 g_aoh[(size_t)M_ * E_];      // attention out split
__device__ __nv_bfloat16 g_aol[(size_t)M_ * E_];

// ---------------------------------------------------------------------------
// PTX helpers (portable: mma.sync + ldmatrix + cp.async, OK on compute_103)
// ---------------------------------------------------------------------------
__device__ __forceinline__ uint32_t smem_u32(const void* p) {
    uint32_t a;
    asm("{ .reg .u64 t; cvta.to.shared.u64 t, %1; cvt.u32.u64 %0, t; }" : "=r"(a) : "l"(p));
    return a;
}
#define CPA16(dst, src) \
    asm volatile("cp.async.cg.shared.global [%0], [%1], 16;" :: "r"(dst), "l"(src) : "memory")
#define CP_COMMIT() asm volatile("cp.async.commit_group;" ::: "memory")
#define CP_WAIT1()  asm volatile("cp.async.wait_group 1;" ::: "memory")

__device__ __forceinline__ void ldsm_x4(uint32_t addr, uint32_t& r0, uint32_t& r1,
                                        uint32_t& r2, uint32_t& r3) {
    asm volatile("ldmatrix.sync.aligned.m8n8.x4.shared.b16 {%0,%1,%2,%3}, [%4];"
                 : "=r"(r0), "=r"(r1), "=r"(r2), "=r"(r3) : "r"(addr));
}
__device__ __forceinline__ void mma_bf16(float* c, const uint32_t* a, const uint32_t* b) {
    asm volatile("mma.sync.aligned.m16n8k16.row.col.f32.bf16.bf16.f32 "
        "{%0,%1,%2,%3}, {%4,%5,%6,%7}, {%8,%9}, {%0,%1,%2,%3};"
        : "+f"(c[0]), "+f"(c[1]), "+f"(c[2]), "+f"(c[3])
        : "r"(a[0]), "r"(a[1]), "r"(a[2]), "r"(a[3]), "r"(b[0]), "r"(b[1]));
}

// ---------------------------------------------------------------------------
// convert: fp32 -> (hi, lo) bf16, 4 elements/thread
// ---------------------------------------------------------------------------
__global__ void convert_split(const float4* __restrict__ in,
                              uint2* __restrict__ hi, uint2* __restrict__ lo, int n4)
{
    int i = blockIdx.x * blockDim.x + threadIdx.x;
    if (i >= n4) return;
    float4 v = in[i];
    __nv_bfloat16 h0 = __float2bfloat16(v.x);
    __nv_bfloat16 h1 = __float2bfloat16(v.y);
    __nv_bfloat16 h2 = __float2bfloat16(v.z);
    __nv_bfloat16 h3 = __float2bfloat16(v.w);
    __nv_bfloat16 l0 = __float2bfloat16(v.x - __bfloat162float(h0));
    __nv_bfloat16 l1 = __float2bfloat16(v.y - __bfloat162float(h1));
    __nv_bfloat16 l2 = __float2bfloat16(v.z - __bfloat162float(h2));
    __nv_bfloat16 l3 = __float2bfloat16(v.w - __bfloat162float(h3));
    uint2 H, L;
    H.x = (uint32_t)__bfloat16_as_ushort(h0) | ((uint32_t)__bfloat16_as_ushort(h1) << 16);
    H.y = (uint32_t)__bfloat16_as_ushort(h2) | ((uint32_t)__bfloat16_as_ushort(h3) << 16);
    L.x = (uint32_t)__bfloat16_as_ushort(l0) | ((uint32_t)__bfloat16_as_ushort(l1) << 16);
    L.y = (uint32_t)__bfloat16_as_ushort(l2) | ((uint32_t)__bfloat16_as_ushort(l3) << 16);
    hi[i] = H;
    lo[i] = L;
}

// W [K,N] fp32 -> W^T [N,K] (hi, lo) bf16, 32x32 smem tile transpose
__global__ void convert_w_t(const float* __restrict__ W,
                            __nv_bfloat16* __restrict__ Th, __nv_bfloat16* __restrict__ Tl,
                            int K, int N)
{
    __shared__ float tile[32][33];
    int n0 = blockIdx.x * 32, k0 = blockIdx.y * 32;
    int tx = threadIdx.x, ty = threadIdx.y;
    for (int i = ty; i < 32; i += 8)
        tile[i][tx] = W[(size_t)(k0 + i) * N + n0 + tx];
    __syncthreads();
    for (int i = ty; i < 32; i += 8) {
        float v = tile[tx][i];
        __nv_bfloat16 h = __float2bfloat16(v);
        Th[(size_t)(n0 + i) * K + k0 + tx] = h;
        Tl[(size_t)(n0 + i) * K + k0 + tx] = __float2bfloat16(v - __bfloat162float(h));
    }
}

// ---------------------------------------------------------------------------
// HMMA GEMM: C[M,N] = A[M,K] @ B^T[N,K] + bias  (split-bf16, 3-term fp32)
// Block 128x128, BK=32, 8 warps (warp tile 32x64), 2-stage cp.async pipeline.
// Smem per stage 32KB: Ah@0, Al@8K, Bh@16K, Bl@24K. Rows of 32 bf16 = 64B =
// 4x16B chunks, chunk swizzled by (chunk ^ (row & 3)).
// ---------------------------------------------------------------------------
__global__ __launch_bounds__(256)
void tc_gemm(const __nv_bfloat16* __restrict__ Ah, const __nv_bfloat16* __restrict__ Al,
             const __nv_bfloat16* __restrict__ Bh, const __nv_bfloat16* __restrict__ Bl,
             const float* __restrict__ bias, float* __restrict__ C,
             int Mtot, int Ntot, int Ktot)
{
    extern __shared__ char smem[];
    uint32_t sbase = smem_u32(smem);
    int tid = threadIdx.x, lane = tid & 31, wid = tid >> 5;
    int wm = wid & 3, wn = wid >> 2;           // warp grid 4(M) x 2(N)
    int m0 = blockIdx.y * 128, n0 = blockIdx.x * 128;

    float acc[2][8][4];
    #pragma unroll
    for (int mi = 0; mi < 2; mi++)
        #pragma unroll
        for (int ni = 0; ni < 8; ni++)
            #pragma unroll
            for (int e = 0; e < 4; e++) acc[mi][ni][e] = 0.f;

    const int NCH = Ktot / 32;

    // loader: 512 16B-chunks per operand buffer, 2 per thread
    auto load_stage = [&](int ch, int st) {
        uint32_t sb = sbase + (uint32_t)st * 32768u;
        int kb = ch * 32;
        #pragma unroll
        for (int u = 0; u < 2; u++) {
            int idx = tid + u * 256;           // 0..511
            int row = idx >> 2, chunk = idx & 3;
            uint32_t soff = (uint32_t)(row * 64 + ((chunk ^ (row & 3)) * 16));
            size_t ga = (size_t)(m0 + row) * Ktot + kb + chunk * 8;
            size_t gb = (size_t)(n0 + row) * Ktot + kb + chunk * 8;
            CPA16(sb +         soff, (const void*)(Ah + ga));
            CPA16(sb + 8192u + soff, (const void*)(Al + ga));
            CPA16(sb + 16384u + soff, (const void*)(Bh + gb));
            CPA16(sb + 24576u + soff, (const void*)(Bl + gb));
        }
    };

    auto compute_stage = [&](int st) {
        uint32_t sA  = sbase + (uint32_t)st * 32768u;
        uint32_t sAl = sA + 8192u;
        uint32_t sB  = sA + 16384u;
        uint32_t sBl = sA + 24576u;
        #pragma unroll
        for (int ks = 0; ks < 2; ks++) {
            uint32_t ah[2][4], al[2][4];
            #pragma unroll
            for (int mi = 0; mi < 2; mi++) {
                int r = wm * 32 + mi * 16 + (lane & 15);
                int chunk = ks * 2 + (lane >> 4);
                uint32_t off = (uint32_t)(r * 64 + ((chunk ^ (r & 3)) * 16));
                ldsm_x4(sA  + off, ah[mi][0], ah[mi][1], ah[mi][2], ah[mi][3]);
                ldsm_x4(sAl + off, al[mi][0], al[mi][1], al[mi][2], al[mi][3]);
            }
            uint32_t bh[8][2], bl[8][2];
            #pragma unroll
            for (int p = 0; p < 4; p++) {
                int r = wn * 64 + p * 16 + (lane & 15);
                int chunk = ks * 2 + (lane >> 4);
                uint32_t off = (uint32_t)(r * 64 + ((chunk ^ (r & 3)) * 16));
                uint32_t t0, t1, t2, t3;
                ldsm_x4(sB + off, t0, t1, t2, t3);
                bh[2*p][0] = t0; bh[2*p][1] = t2; bh[2*p+1][0] = t1; bh[2*p+1][1] = t3;
                ldsm_x4(sBl + off, t0, t1, t2, t3);
                bl[2*p][0] = t0; bl[2*p][1] = t2; bl[2*p+1][0] = t1; bl[2*p+1][1] = t3;
            }
            #pragma unroll
            for (int mi = 0; mi < 2; mi++)
                #pragma unroll
                for (int ni = 0; ni < 8; ni++) {
                    mma_bf16(acc[mi][ni], ah[mi], bh[ni]);
                    mma_bf16(acc[mi][ni], ah[mi], bl[ni]);
                    mma_bf16(acc[mi][ni], al[mi], bh[ni]);
                }
        }
    };

    load_stage(0, 0); CP_COMMIT();
    load_stage(1, 1); CP_COMMIT();

    for (int ch = 0; ch < NCH; ch++) {
        CP_WAIT1();
        __syncthreads();
        compute_stage(ch & 1);
        __syncthreads();
        if (ch + 2 < NCH) load_stage(ch + 2, ch & 1);
        CP_COMMIT();
    }

    // Epilogue: +bias, float2 stores
    #pragma unroll
    for (int mi = 0; mi < 2; mi++) {
        #pragma unroll
        for (int ni = 0; ni < 8; ni++) {
            int row = m0 + wm * 32 + mi * 16 + (lane >> 2);
            int col = n0 + wn * 64 + ni * 8 + (lane & 3) * 2;
            float2 bv = *(const float2*)&bias[col];
            float2 v0 = {acc[mi][ni][0] + bv.x, acc[mi][ni][1] + bv.y};
            float2 v1 = {acc[mi][ni][2] + bv.x, acc[mi][ni][3] + bv.y};
            *(float2*)&C[(size_t)row * Ntot + col] = v0;
            *(float2*)&C[(size_t)(row + 8) * Ntot + col] = v1;
        }
    }
}

// ---------------------------------------------------------------------------
// RoPE + split: g_qkv [B,N,3,H,D] -> g_q/g_k (roped), g_v, each [B,H,N,D].
// ---------------------------------------------------------------------------
__global__ void rope_split(const float* __restrict__ qkv,
                           float* __restrict__ Qo, float* __restrict__ Ko,
                           float* __restrict__ Vo)
{
    int idx = blockIdx.x * blockDim.x + threadIdx.x;
    const int total = B_ * H_ * N_ * 32;
    if (idx >= total) return;
    int d2 = idx & 31;
    int rest = idx >> 5;
    int t = rest & (N_ - 1);
    int rest2 = rest >> 10;
    int h = rest2 % H_;
    int b = rest2 / H_;

    float f = (float)h * exp2f(-(float)d2 * (13.287712379549449f / 32.0f));
    float s, c;
    sincosf(f, &s, &c);

    const float* base = qkv + ((size_t)(b * N_ + t)) * (3 * E_) + h * D_;
    float q1 = base[d2],        q2 = base[d2 + 32];
    float k1 = base[E_ + d2],   k2 = base[E_ + d2 + 32];
    float v1 = base[2*E_ + d2], v2 = base[2*E_ + d2 + 32];

    size_t ob = ((size_t)((b * H_ + h) * N_ + t)) * D_;
    Qo[ob + d2]      = q1 * c - q2 * s;
    Qo[ob + d2 + 32] = q2 * c + q1 * s;
    Ko[ob + d2]      = k1 * c - k2 * s;
    Ko[ob + d2 + 32] = k2 * c + k1 * s;
    Vo[ob + d2]      = v1;
    Vo[ob + d2 + 32] = v2;
}

// ---------------------------------------------------------------------------
// Flash attention, fp32 (unchanged)
// ---------------------------------------------------------------------------
#define SM_STRIDE 68
__global__ __launch_bounds__(256) void attn_kernel(
    const float* __restrict__ Q, const float* __restrict__ K,
    const float* __restrict__ V, float* __restrict__ O)
{
    extern __shared__ float sm[];
    float* QsT = sm;
    float* KsT = sm + 64 * SM_STRIDE;
    float* Vs  = sm + 2 * 64 * SM_STRIDE;
    float* PsT = sm + 3 * 64 * SM_STRIDE;

    int tid = threadIdx.x;
    int bh = blockIdx.y;
    int b = bh / H_, h = bh % H_;
    int q0 = blockIdx.x * 64;
    const float* Qb = Q + (size_t)bh * N_ * D_;
    const float* Kb = K + (size_t)bh * N_ * D_;
    const float* Vb = V + (size_t)bh * N_ * D_;

    const float scale = 0.125f;
    for (int idx = tid; idx < 64 * 64; idx += 256) {
        int r = idx >> 6, d = idx & 63;
        QsT[d * SM_STRIDE + r] = Qb[(size_t)(q0 + r) * D_ + d] * scale;
    }

    int ty = tid >> 4, tx = tid & 15;
    int r0 = ty * 4, c0 = tx * 4;

    float o[4][4];
    #pragma unroll
    for (int i = 0; i < 4; i++)
        #pragma unroll
        for (int j = 0; j < 4; j++) o[i][j] = 0.f;
    float mrow[4] = {-1e30f, -1e30f, -1e30f, -1e30f};
    float lrow[4] = {0.f, 0.f, 0.f, 0.f};

    for (int jt = 0; jt < N_; jt += 64) {
        __syncthreads();
        for (int idx = tid; idx < 64 * 64; idx += 256) {
            int r = idx >> 6, d = idx & 63;
            float kv = Kb[(size_t)(jt + r) * D_ + d];
            float vv = Vb[(size_t)(jt + r) * D_ + d];
            KsT[d * SM_STRIDE + r] = kv;
            Vs[r * SM_STRIDE + d]  = vv;
        }
        __syncthreads();

        float s[4][4];
        #pragma unroll
        for (int i = 0; i < 4; i++)
            #pragma unroll
            for (int j = 0; j < 4; j++) s[i][j] = 0.f;
        #pragma unroll 8
        for (int k = 0; k < 64; k++) {
            float4 qa = *(float4*)&QsT[k * SM_STRIDE + r0];
            float4 kb = *(float4*)&KsT[k * SM_STRIDE + c0];
            float qq[4] = {qa.x, qa.y, qa.z, qa.w};
            float kk[4] = {kb.x, kb.y, kb.z, kb.w};
            #pragma unroll
            for (int i = 0; i < 4; i++)
                #pragma unroll
                for (int j = 0; j < 4; j++)
                    s[i][j] += qq[i] * kk[j];
        }

        float fac[4];
        #pragma unroll
        for (int i = 0; i < 4; i++) {
            float mt = fmaxf(fmaxf(s[i][0], s[i][1]), fmaxf(s[i][2], s[i][3]));
            #pragma unroll
            for (int off = 8; off; off >>= 1)
                mt = fmaxf(mt, __shfl_xor_sync(0xffffffffu, mt, off));
            float mnew = fmaxf(mrow[i], mt);
            fac[i] = __expf(mrow[i] - mnew);
            mrow[i] = mnew;
            float ps = 0.f;
            #pragma unroll
            for (int j = 0; j < 4; j++) {
                float p = __expf(s[i][j] - mnew);
                s[i][j] = p;
                ps += p;
            }
            #pragma unroll
            for (int off = 8; off; off >>= 1)
                ps += __shfl_xor_sync(0xffffffffu, ps, off);
            lrow[i] = lrow[i] * fac[i] + ps;
            #pragma unroll
            for (int j = 0; j < 4; j++) o[i][j] *= fac[i];
        }

        #pragma unroll
        for (int j = 0; j < 4; j++) {
            float4 pv = {s[0][j], s[1][j], s[2][j], s[3][j]};
            *(float4*)&PsT[(c0 + j) * SM_STRIDE + r0] = pv;
        }
        __syncthreads();

        #pragma unroll 8
        for (int j = 0; j < 64; j++) {
            float4 pa = *(float4*)&PsT[j * SM_STRIDE + r0];
            float4 vb = *(float4*)&Vs[j * SM_STRIDE + c0];
            float pp[4] = {pa.x, pa.y, pa.z, pa.w};
            float vv[4] = {vb.x, vb.y, vb.z, vb.w};
            #pragma unroll
            for (int i = 0; i < 4; i++)
                #pragma unroll
                for (int jj = 0; jj < 4; jj++)
                    o[i][jj] += pp[i] * vv[jj];
        }
    }

    #pragma unroll
    for (int i = 0; i < 4; i++) {
        float inv = 1.0f / lrow[i];
        int row = q0 + r0 + i;
        float4 ov = {o[i][0] * inv, o[i][1] * inv, o[i][2] * inv, o[i][3] * inv};
        *(float4*)&O[(size_t)(b * N_ + row) * E_ + h * D_ + c0] = ov;
    }
}

// ---------------------------------------------------------------------------
extern "C" void kernel_launch(void* const* d_in, const int* in_sizes, int n_in,
                              void* d_out, int out_size)
{
    (void)in_sizes; (void)n_in; (void)out_size;
    const float* x      = (const float*)d_in[0];
    const float* w_qkv  = (const float*)d_in[1];
    const float* b_qkv  = (const float*)d_in[2];
    const float* w_proj = (const float*)d_in[3];
    const float* b_proj = (const float*)d_in[4];
    float* out = (float*)d_out;

    float *qkv, *q, *k, *v, *ao;
    __nv_bfloat16 *xh, *xl, *wqh, *wql, *wph, *wpl, *aoh, *aol;
    cudaGetSymbolAddress((void**)&qkv, g_qkv);
    cudaGetSymbolAddress((void**)&q,   g_q);
    cudaGetSymbolAddress((void**)&k,   g_k);
    cudaGetSymbolAddress((void**)&v,   g_v);
    cudaGetSymbolAddress((void**)&ao,  g_ao);
    cudaGetSymbolAddress((void**)&xh,  g_xh);
    cudaGetSymbolAddress((void**)&xl,  g_xl);
    cudaGetSymbolAddress((void**)&wqh, g_wqh);
    cudaGetSymbolAddress((void**)&wql, g_wql);
    cudaGetSymbolAddress((void**)&wph, g_wph);
    cudaGetSymbolAddress((void**)&wpl, g_wpl);
    cudaGetSymbolAddress((void**)&aoh, g_aoh);
    cudaGetSymbolAddress((void**)&aol, g_aol);

    const int GEMM_SMEM = 2 * 32768;
    cudaFuncSetAttribute(tc_gemm, cudaFuncAttributeMaxDynamicSharedMemorySize, GEMM_SMEM);

    // 1) split-convert x
    {
        int n4 = M_ * E_ / 4;
        convert_split<<<(n4 + 255) / 256, 256>>>((const float4*)x, (uint2*)xh, (uint2*)xl, n4);
    }
    // 2) transpose+split weights
    {
        dim3 blk(32, 8);
        convert_w_t<<<dim3(3 * E_ / 32, E_ / 32), blk>>>(w_qkv, wqh, wql, E_, 3 * E_);
        convert_w_t<<<dim3(E_ / 32, E_ / 32), blk>>>(w_proj, wph, wpl, E_, E_);
    }
    // 3) QKV GEMM (mma.sync bf16 split)
    {
        dim3 grid(3 * E_ / 128, M_ / 128);
        tc_gemm<<<grid, 256, GEMM_SMEM>>>(xh, xl, wqh, wql, b_qkv, qkv, M_, 3 * E_, E_);
    }
    // 4) RoPE + split
    {
        int total = B_ * H_ * N_ * 32;
        rope_split<<<(total + 255) / 256, 256>>>(qkv, q, k, v);
    }
    // 5) Attention (fp32 flash)
    {
        size_t smem = 4 * 64 * SM_STRIDE * sizeof(float);
        cudaFuncSetAttribute(attn_kernel, cudaFuncAttributeMaxDynamicSharedMemorySize, (int)smem);
        dim3 grid(N_ / 64, B_ * H_);
        attn_kernel<<<grid, 256, smem>>>(q, k, v, ao);
    }
    // 6) split-convert attention output
    {
        int n4 = M_ * E_ / 4;
        convert_split<<<(n4 + 255) / 256, 256>>>((const float4*)ao, (uint2*)aoh, (uint2*)aol, n4);
    }
    // 7) projection GEMM (mma.sync bf16 split)
    {
        dim3 grid(E_ / 128, M_ / 128);
        tc_gemm<<<grid, 256, GEMM_SMEM>>>(aoh, aol, wph, wpl, b_proj, out, M_, E_, E_);
    }
}

// round 4
// speedup vs baseline: 2.5415x; 1.7416x over previous
#include <cuda_runtime.h>
#include <cuda_bf16.h>
#include <math.h>
#include <stdint.h>

#define B_ 8
#define N_ 1024
#define E_ 768
#define H_ 12
#define D_ 64
#define M_ (B_*N_)   // 8192

// ---------------------------------------------------------------------------
// Scratch (__device__ globals; no allocations allowed)
// ---------------------------------------------------------------------------
__device__ float g_qkv[(size_t)M_ * 3 * E_];          // [M, 2304]
__device__ float g_ao[(size_t)M_ * E_];               // attention out [M,768]
__device__ __nv_bfloat16 g_xh[(size_t)M_ * E_];
__device__ __nv_bfloat16 g_xl[(size_t)M_ * E_];
__device__ __nv_bfloat16 g_wqh[(size_t)3*E_ * E_];
__device__ __nv_bfloat16 g_wql[(size_t)3*E_ * E_];
__device__ __nv_bfloat16 g_wph[(size_t)E_ * E_];
__device__ __nv_bfloat16 g_wpl[(size_t)E_ * E_];
__device__ __nv_bfloat16 g_aoh[(size_t)M_ * E_];
__device__ __nv_bfloat16 g_aol[(size_t)M_ * E_];
// attention operands: Q/K [bh][n][64] hi/lo, Vt [bh][64][n] hi/lo
__device__ __nv_bfloat16 g_qh2[(size_t)B_*H_*N_*D_];
__device__ __nv_bfloat16 g_ql2[(size_t)B_*H_*N_*D_];
__device__ __nv_bfloat16 g_kh2[(size_t)B_*H_*N_*D_];
__device__ __nv_bfloat16 g_kl2[(size_t)B_*H_*N_*D_];
__device__ __nv_bfloat16 g_vth[(size_t)B_*H_*D_*N_];
__device__ __nv_bfloat16 g_vtl[(size_t)B_*H_*D_*N_];

// ---------------------------------------------------------------------------
// PTX helpers
// ---------------------------------------------------------------------------
__device__ __forceinline__ uint32_t smem_u32(const void* p) {
    uint32_t a;
    asm("{ .reg .u64 t; cvta.to.shared.u64 t, %1; cvt.u32.u64 %0, t; }" : "=r"(a) : "l"(p));
    return a;
}
#define CPA16(dst, src) \
    asm volatile("cp.async.cg.shared.global [%0], [%1], 16;" :: "r"(dst), "l"(src) : "memory")
#define CP_COMMIT() asm volatile("cp.async.commit_group;" ::: "memory")
#define CP_WAIT1()  asm volatile("cp.async.wait_group 1;" ::: "memory")

__device__ __forceinline__ void ldsm_x4(uint32_t addr, uint32_t& r0, uint32_t& r1,
                                        uint32_t& r2, uint32_t& r3) {
    asm volatile("ldmatrix.sync.aligned.m8n8.x4.shared.b16 {%0,%1,%2,%3}, [%4];"
                 : "=r"(r0), "=r"(r1), "=r"(r2), "=r"(r3) : "r"(addr));
}
__device__ __forceinline__ void mma_bf16(float* c, const uint32_t* a, const uint32_t* b) {
    asm volatile("mma.sync.aligned.m16n8k16.row.col.f32.bf16.bf16.f32 "
        "{%0,%1,%2,%3}, {%4,%5,%6,%7}, {%8,%9}, {%0,%1,%2,%3};"
        : "+f"(c[0]), "+f"(c[1]), "+f"(c[2]), "+f"(c[3])
        : "r"(a[0]), "r"(a[1]), "r"(a[2]), "r"(a[3]), "r"(b[0]), "r"(b[1]));
}
__device__ __forceinline__ uint32_t pack_bf16x2(float lo, float hi) {
    __nv_bfloat162 t = __floats2bfloat162_rn(lo, hi);
    return *(uint32_t*)&t;
}

// ---------------------------------------------------------------------------
// convert: fp32 -> (hi, lo) bf16
// ---------------------------------------------------------------------------
__global__ void convert_split(const float4* __restrict__ in,
                              uint2* __restrict__ hi, uint2* __restrict__ lo, int n4)
{
    int i = blockIdx.x * blockDim.x + threadIdx.x;
    if (i >= n4) return;
    float4 v = in[i];
    __nv_bfloat16 h0 = __float2bfloat16(v.x);
    __nv_bfloat16 h1 = __float2bfloat16(v.y);
    __nv_bfloat16 h2 = __float2bfloat16(v.z);
    __nv_bfloat16 h3 = __float2bfloat16(v.w);
    __nv_bfloat16 l0 = __float2bfloat16(v.x - __bfloat162float(h0));
    __nv_bfloat16 l1 = __float2bfloat16(v.y - __bfloat162float(h1));
    __nv_bfloat16 l2 = __float2bfloat16(v.z - __bfloat162float(h2));
    __nv_bfloat16 l3 = __float2bfloat16(v.w - __bfloat162float(h3));
    uint2 H, L;
    H.x = (uint32_t)__bfloat16_as_ushort(h0) | ((uint32_t)__bfloat16_as_ushort(h1) << 16);
    H.y = (uint32_t)__bfloat16_as_ushort(h2) | ((uint32_t)__bfloat16_as_ushort(h3) << 16);
    L.x = (uint32_t)__bfloat16_as_ushort(l0) | ((uint32_t)__bfloat16_as_ushort(l1) << 16);
    L.y = (uint32_t)__bfloat16_as_ushort(l2) | ((uint32_t)__bfloat16_as_ushort(l3) << 16);
    hi[i] = H;
    lo[i] = L;
}

__global__ void convert_w_t(const float* __restrict__ W,
                            __nv_bfloat16* __restrict__ Th, __nv_bfloat16* __restrict__ Tl,
                            int K, int N)
{
    __shared__ float tile[32][33];
    int n0 = blockIdx.x * 32, k0 = blockIdx.y * 32;
    int tx = threadIdx.x, ty = threadIdx.y;
    for (int i = ty; i < 32; i += 8)
        tile[i][tx] = W[(size_t)(k0 + i) * N + n0 + tx];
    __syncthreads();
    for (int i = ty; i < 32; i += 8) {
        float v = tile[tx][i];
        __nv_bfloat16 h = __float2bfloat16(v);
        Th[(size_t)(n0 + i) * K + k0 + tx] = h;
        Tl[(size_t)(n0 + i) * K + k0 + tx] = __float2bfloat16(v - __bfloat162float(h));
    }
}

// ---------------------------------------------------------------------------
// Dense HMMA GEMM (unchanged from R3)
// ---------------------------------------------------------------------------
__global__ __launch_bounds__(256)
void tc_gemm(const __nv_bfloat16* __restrict__ Ah, const __nv_bfloat16* __restrict__ Al,
             const __nv_bfloat16* __restrict__ Bh, const __nv_bfloat16* __restrict__ Bl,
             const float* __restrict__ bias, float* __restrict__ C,
             int Mtot, int Ntot, int Ktot)
{
    extern __shared__ char smem[];
    uint32_t sbase = smem_u32(smem);
    int tid = threadIdx.x, lane = tid & 31, wid = tid >> 5;
    int wm = wid & 3, wn = wid >> 2;
    int m0 = blockIdx.y * 128, n0 = blockIdx.x * 128;

    float acc[2][8][4];
    #pragma unroll
    for (int mi = 0; mi < 2; mi++)
        #pragma unroll
        for (int ni = 0; ni < 8; ni++)
            #pragma unroll
            for (int e = 0; e < 4; e++) acc[mi][ni][e] = 0.f;

    const int NCH = Ktot / 32;

    auto load_stage = [&](int ch, int st) {
        uint32_t sb = sbase + (uint32_t)st * 32768u;
        int kb = ch * 32;
        #pragma unroll
        for (int u = 0; u < 2; u++) {
            int idx = tid + u * 256;
            int row = idx >> 2, chunk = idx & 3;
            uint32_t soff = (uint32_t)(row * 64 + ((chunk ^ (row & 3)) * 16));
            size_t ga = (size_t)(m0 + row) * Ktot + kb + chunk * 8;
            size_t gb = (size_t)(n0 + row) * Ktot + kb + chunk * 8;
            CPA16(sb +         soff, (const void*)(Ah + ga));
            CPA16(sb + 8192u + soff, (const void*)(Al + ga));
            CPA16(sb + 16384u + soff, (const void*)(Bh + gb));
            CPA16(sb + 24576u + soff, (const void*)(Bl + gb));
        }
    };

    auto compute_stage = [&](int st) {
        uint32_t sA  = sbase + (uint32_t)st * 32768u;
        uint32_t sAl = sA + 8192u;
        uint32_t sB  = sA + 16384u;
        uint32_t sBl = sA + 24576u;
        #pragma unroll
        for (int ks = 0; ks < 2; ks++) {
            uint32_t ah[2][4], al[2][4];
            #pragma unroll
            for (int mi = 0; mi < 2; mi++) {
                int r = wm * 32 + mi * 16 + (lane & 15);
                int chunk = ks * 2 + (lane >> 4);
                uint32_t off = (uint32_t)(r * 64 + ((chunk ^ (r & 3)) * 16));
                ldsm_x4(sA  + off, ah[mi][0], ah[mi][1], ah[mi][2], ah[mi][3]);
                ldsm_x4(sAl + off, al[mi][0], al[mi][1], al[mi][2], al[mi][3]);
            }
            uint32_t bh[8][2], bl[8][2];
            #pragma unroll
            for (int p = 0; p < 4; p++) {
                int r = wn * 64 + p * 16 + (lane & 15);
                int chunk = ks * 2 + (lane >> 4);
                uint32_t off = (uint32_t)(r * 64 + ((chunk ^ (r & 3)) * 16));
                uint32_t t0, t1, t2, t3;
                ldsm_x4(sB + off, t0, t1, t2, t3);
                bh[2*p][0] = t0; bh[2*p][1] = t2; bh[2*p+1][0] = t1; bh[2*p+1][1] = t3;
                ldsm_x4(sBl + off, t0, t1, t2, t3);
                bl[2*p][0] = t0; bl[2*p][1] = t2; bl[2*p+1][0] = t1; bl[2*p+1][1] = t3;
            }
            #pragma unroll
            for (int mi = 0; mi < 2; mi++)
                #pragma unroll
                for (int ni = 0; ni < 8; ni++) {
                    mma_bf16(acc[mi][ni], ah[mi], bh[ni]);
                    mma_bf16(acc[mi][ni], ah[mi], bl[ni]);
                    mma_bf16(acc[mi][ni], al[mi], bh[ni]);
                }
        }
    };

    load_stage(0, 0); CP_COMMIT();
    load_stage(1, 1); CP_COMMIT();

    for (int ch = 0; ch < NCH; ch++) {
        CP_WAIT1();
        __syncthreads();
        compute_stage(ch & 1);
        __syncthreads();
        if (ch + 2 < NCH) load_stage(ch + 2, ch & 1);
        CP_COMMIT();
    }

    #pragma unroll
    for (int mi = 0; mi < 2; mi++) {
        #pragma unroll
        for (int ni = 0; ni < 8; ni++) {
            int row = m0 + wm * 32 + mi * 16 + (lane >> 2);
            int col = n0 + wn * 64 + ni * 8 + (lane & 3) * 2;
            float2 bv = *(const float2*)&bias[col];
            float2 v0 = {acc[mi][ni][0] + bv.x, acc[mi][ni][1] + bv.y};
            float2 v1 = {acc[mi][ni][2] + bv.x, acc[mi][ni][3] + bv.y};
            *(float2*)&C[(size_t)row * Ntot + col] = v0;
            *(float2*)&C[(size_t)(row + 8) * Ntot + col] = v1;
        }
    }
}

// ---------------------------------------------------------------------------
// RoPE + split + transpose: qkv [B,N,3,H,D] ->
//   Qh/Ql (roped, pre-scaled), Kh/Kl [bh][n][64];  Vth/Vtl [bh][64][n]
// Block: one (bh, 128-token tile).
// ---------------------------------------------------------------------------
__global__ __launch_bounds__(256) void rope_split_v2(
    const float* __restrict__ qkv,
    __nv_bfloat16* __restrict__ Qh, __nv_bfloat16* __restrict__ Ql,
    __nv_bfloat16* __restrict__ Kh, __nv_bfloat16* __restrict__ Kl,
    __nv_bfloat16* __restrict__ Vth, __nv_bfloat16* __restrict__ Vtl)
{
    __shared__ float sv[64][129];
    int bh = blockIdx.y;
    int b = bh / H_, h = bh % H_;
    int t0 = blockIdx.x * 128;
    int tid = threadIdx.x;

    for (int i = tid; i < 128 * 32; i += 256) {
        int t = i >> 5, d2 = i & 31;
        float f = (float)h * exp2f(-(float)d2 * (13.287712379549449f / 32.0f));
        float s, c;
        sincosf(f, &s, &c);
        const float* base = qkv + ((size_t)(b * N_ + t0 + t)) * (3 * E_) + h * D_;
        float q1 = base[d2],        q2 = base[d2 + 32];
        float k1 = base[E_ + d2],   k2 = base[E_ + d2 + 32];
        float v1 = base[2*E_ + d2], v2 = base[2*E_ + d2 + 32];

        float qr1 = (q1 * c - q2 * s) * 0.125f;
        float qr2 = (q2 * c + q1 * s) * 0.125f;
        float kr1 = k1 * c - k2 * s;
        float kr2 = k2 * c + k1 * s;

        size_t ob = ((size_t)bh * N_ + t0 + t) * D_;
        __nv_bfloat16 hh;
        hh = __float2bfloat16(qr1); Qh[ob + d2] = hh;
        Ql[ob + d2] = __float2bfloat16(qr1 - __bfloat162float(hh));
        hh = __float2bfloat16(qr2); Qh[ob + d2 + 32] = hh;
        Ql[ob + d2 + 32] = __float2bfloat16(qr2 - __bfloat162float(hh));
        hh = __float2bfloat16(kr1); Kh[ob + d2] = hh;
        Kl[ob + d2] = __float2bfloat16(kr1 - __bfloat162float(hh));
        hh = __float2bfloat16(kr2); Kh[ob + d2 + 32] = hh;
        Kl[ob + d2 + 32] = __float2bfloat16(kr2 - __bfloat162float(hh));

        sv[d2][t] = v1;
        sv[d2 + 32][t] = v2;
    }
    __syncthreads();

    // write Vt: rows = d, 4 cols per unit
    for (int i = tid; i < 64 * 32; i += 256) {
        int d = i >> 5, c4 = (i & 31) * 4;
        float v0 = sv[d][c4], v1 = sv[d][c4+1], v2 = sv[d][c4+2], v3 = sv[d][c4+3];
        __nv_bfloat16 h0 = __float2bfloat16(v0), h1 = __float2bfloat16(v1);
        __nv_bfloat16 h2 = __float2bfloat16(v2), h3 = __float2bfloat16(v3);
        uint2 Hv, Lv;
        Hv.x = (uint32_t)__bfloat16_as_ushort(h0) | ((uint32_t)__bfloat16_as_ushort(h1) << 16);
        Hv.y = (uint32_t)__bfloat16_as_ushort(h2) | ((uint32_t)__bfloat16_as_ushort(h3) << 16);
        Lv.x = (uint32_t)__bfloat16_as_ushort(__float2bfloat16(v0 - __bfloat162float(h0)))
             | ((uint32_t)__bfloat16_as_ushort(__float2bfloat16(v1 - __bfloat162float(h1))) << 16);
        Lv.y = (uint32_t)__bfloat16_as_ushort(__float2bfloat16(v2 - __bfloat162float(h2)))
             | ((uint32_t)__bfloat16_as_ushort(__float2bfloat16(v3 - __bfloat162float(h3))) << 16);
        size_t ob = ((size_t)bh * 64 + d) * N_ + t0 + c4;
        *(uint2*)(Vth + ob) = Hv;
        *(uint2*)(Vtl + ob) = Lv;
    }
}

// ---------------------------------------------------------------------------
// Tensor-core flash attention.
// CTA: 128 queries of one (b,h). 8 warps x 16 query rows. Key blocks of 64,
// 16 iterations, 2-stage cp.async pipeline. Split-bf16 3-term for QK and PV.
// Smem: Qh@0, Ql@16K, stage st@32K+st*32K: {Kh, Kl, Vth, Vtl} x 8KB.
// ---------------------------------------------------------------------------
__global__ __launch_bounds__(256, 2) void attn_mma(
    const __nv_bfloat16* __restrict__ Qh, const __nv_bfloat16* __restrict__ Ql,
    const __nv_bfloat16* __restrict__ Kh, const __nv_bfloat16* __restrict__ Kl,
    const __nv_bfloat16* __restrict__ Vth, const __nv_bfloat16* __restrict__ Vtl,
    float* __restrict__ O)
{
    extern __shared__ char smem[];
    uint32_t sb = smem_u32(smem);
    const uint32_t oQh = 0, oQl = 16384, oStage = 32768;

    int tid = threadIdx.x, lane = tid & 31, wq = tid >> 5;
    int bh = blockIdx.y;
    int q0 = blockIdx.x * 128;
    int b = bh / H_, h = bh % H_;

    const __nv_bfloat16* Qhb = Qh + ((size_t)bh * N_ + q0) * D_;
    const __nv_bfloat16* Qlb = Ql + ((size_t)bh * N_ + q0) * D_;
    const __nv_bfloat16* Khb = Kh + (size_t)bh * N_ * D_;
    const __nv_bfloat16* Klb = Kl + (size_t)bh * N_ * D_;
    const __nv_bfloat16* Vhb = Vth + (size_t)bh * D_ * N_;
    const __nv_bfloat16* Vlb = Vtl + (size_t)bh * D_ * N_;

    // Q load (both splits): 128 rows x 8 chunks each
    for (int u = tid; u < 2048; u += 256) {
        int split = u >> 10;
        int idx = u & 1023;
        int r = idx >> 3, chunk = idx & 7;
        uint32_t off = (uint32_t)(r * 128 + ((chunk ^ (r & 7)) * 16));
        const __nv_bfloat16* src = (split ? Qlb : Qhb) + (size_t)r * D_ + chunk * 8;
        CPA16(sb + (split ? oQl : oQh) + off, (const void*)src);
    }

    auto load_stage = [&](int it, int st) {
        int jt = it * 64;
        uint32_t s0 = sb + oStage + (uint32_t)st * 32768u;
        for (int u = tid; u < 2048; u += 256) {
            int part = u >> 9;        // 0 kh, 1 kl, 2 vth, 3 vtl
            int idx = u & 511;
            int r = idx >> 3, chunk = idx & 7;
            uint32_t off = (uint32_t)(r * 128 + ((chunk ^ (r & 7)) * 16));
            const __nv_bfloat16* src;
            if (part == 0)      src = Khb + (size_t)(jt + r) * D_ + chunk * 8;
            else if (part == 1) src = Klb + (size_t)(jt + r) * D_ + chunk * 8;
            else if (part == 2) src = Vhb + (size_t)r * N_ + jt + chunk * 8;
            else                src = Vlb + (size_t)r * N_ + jt + chunk * 8;
            CPA16(s0 + (uint32_t)part * 8192u + off, (const void*)src);
        }
    };

    float o[8][4];
    #pragma unroll
    for (int i = 0; i < 8; i++)
        #pragma unroll
        for (int j = 0; j < 4; j++) o[i][j] = 0.f;
    float m0v = -1e30f, m1v = -1e30f, l0 = 0.f, l1 = 0.f;

    load_stage(0, 0); CP_COMMIT();
    load_stage(1, 1); CP_COMMIT();

    for (int it = 0; it < 16; it++) {
        CP_WAIT1();
        __syncthreads();
        uint32_t sK = sb + oStage + (uint32_t)(it & 1) * 32768u;

        // ---- S = Q K^T (scaled), fp32, 8 n-tiles ----
        float c[8][4];
        #pragma unroll
        for (int i = 0; i < 8; i++)
            #pragma unroll
            for (int j = 0; j < 4; j++) c[i][j] = 0.f;

        #pragma unroll
        for (int ks = 0; ks < 4; ks++) {
            int chunk = ks * 2 + (lane >> 4);
            int rq = wq * 16 + (lane & 15);
            uint32_t offq = (uint32_t)(rq * 128 + ((chunk ^ (rq & 7)) * 16));
            uint32_t ah[4], al[4];
            ldsm_x4(sb + oQh + offq, ah[0], ah[1], ah[2], ah[3]);
            ldsm_x4(sb + oQl + offq, al[0], al[1], al[2], al[3]);
            #pragma unroll
            for (int p = 0; p < 4; p++) {
                int rk = p * 16 + (lane & 15);
                uint32_t offk = (uint32_t)(rk * 128 + ((chunk ^ (rk & 7)) * 16));
                uint32_t t0, t1, t2, t3;
                uint32_t bh0[2], bh1[2], bl0[2], bl1[2];
                ldsm_x4(sK + offk, t0, t1, t2, t3);
                bh0[0] = t0; bh0[1] = t2; bh1[0] = t1; bh1[1] = t3;
                ldsm_x4(sK + 8192u + offk, t0, t1, t2, t3);
                bl0[0] = t0; bl0[1] = t2; bl1[0] = t1; bl1[1] = t3;
                mma_bf16(c[2*p],   ah, bh0);
                mma_bf16(c[2*p],   ah, bl0);
                mma_bf16(c[2*p],   al, bh0);
                mma_bf16(c[2*p+1], ah, bh1);
                mma_bf16(c[2*p+1], ah, bl1);
                mma_bf16(c[2*p+1], al, bh1);
            }
        }

        // ---- online softmax (two row-halves per thread) ----
        {
            float mt0 = -1e30f, mt1 = -1e30f;
            #pragma unroll
            for (int t = 0; t < 8; t++) {
                mt0 = fmaxf(mt0, fmaxf(c[t][0], c[t][1]));
                mt1 = fmaxf(mt1, fmaxf(c[t][2], c[t][3]));
            }
            mt0 = fmaxf(mt0, __shfl_xor_sync(0xffffffffu, mt0, 1));
            mt0 = fmaxf(mt0, __shfl_xor_sync(0xffffffffu, mt0, 2));
            mt1 = fmaxf(mt1, __shfl_xor_sync(0xffffffffu, mt1, 1));
            mt1 = fmaxf(mt1, __shfl_xor_sync(0xffffffffu, mt1, 2));
            float mn0 = fmaxf(m0v, mt0), mn1 = fmaxf(m1v, mt1);
            float f0 = __expf(m0v - mn0), f1 = __expf(m1v - mn1);
            m0v = mn0; m1v = mn1;
            float ps0 = 0.f, ps1 = 0.f;
            #pragma unroll
            for (int t = 0; t < 8; t++) {
                c[t][0] = __expf(c[t][0] - mn0); ps0 += c[t][0];
                c[t][1] = __expf(c[t][1] - mn0); ps0 += c[t][1];
                c[t][2] = __expf(c[t][2] - mn1); ps1 += c[t][2];
                c[t][3] = __expf(c[t][3] - mn1); ps1 += c[t][3];
            }
            ps0 += __shfl_xor_sync(0xffffffffu, ps0, 1);
            ps0 += __shfl_xor_sync(0xffffffffu, ps0, 2);
            ps1 += __shfl_xor_sync(0xffffffffu, ps1, 1);
            ps1 += __shfl_xor_sync(0xffffffffu, ps1, 2);
            l0 = l0 * f0 + ps0;
            l1 = l1 * f1 + ps1;
            #pragma unroll
            for (int t = 0; t < 8; t++) {
                o[t][0] *= f0; o[t][1] *= f0;
                o[t][2] *= f1; o[t][3] *= f1;
            }
        }

        // ---- P fragments (hi/lo), C-layout -> A-layout ----
        uint32_t aph[4][4], apl[4][4];
        #pragma unroll
        for (int s = 0; s < 4; s++) {
            #pragma unroll
            for (int half = 0; half < 2; half++) {
                int t = 2 * s + half;
                float p0 = c[t][0], p1 = c[t][1], p2 = c[t][2], p3 = c[t][3];
                __nv_bfloat16 h0 = __float2bfloat16(p0), h1 = __float2bfloat16(p1);
                __nv_bfloat16 h2 = __float2bfloat16(p2), h3 = __float2bfloat16(p3);
                aph[s][half * 2 + 0] =
                    (uint32_t)__bfloat16_as_ushort(h0) | ((uint32_t)__bfloat16_as_ushort(h1) << 16);
                aph[s][half * 2 + 1] =
                    (uint32_t)__bfloat16_as_ushort(h2) | ((uint32_t)__bfloat16_as_ushort(h3) << 16);
                apl[s][half * 2 + 0] = pack_bf16x2(p0 - __bfloat162float(h0),
                                                   p1 - __bfloat162float(h1));
                apl[s][half * 2 + 1] = pack_bf16x2(p2 - __bfloat162float(h2),
                                                   p3 - __bfloat162float(h3));
            }
        }
        // reorder: A-frag = {a01(r,klo), a23(r+8,klo), a45(r,khi), a67(r+8,khi)}
        // built above as {tile2s:c01, tile2s:c23, tile2s+1:c01, tile2s+1:c23}
        // tile2s cols = k 0..7 (lo), tile2s+1 = k 8..15 (hi)  ->  matches.

        // ---- O += P V ----
        #pragma unroll
        for (int s = 0; s < 4; s++) {
            int chunk = s * 2 + (lane >> 4);
            #pragma unroll
            for (int p = 0; p < 4; p++) {
                int rd = p * 16 + (lane & 15);
                uint32_t off = (uint32_t)(rd * 128 + ((chunk ^ (rd & 7)) * 16));
                uint32_t t0, t1, t2, t3;
                uint32_t bh0[2], bh1[2], bl0[2], bl1[2];
                ldsm_x4(sK + 16384u + off, t0, t1, t2, t3);
                bh0[0] = t0; bh0[1] = t2; bh1[0] = t1; bh1[1] = t3;
                ldsm_x4(sK + 24576u + off, t0, t1, t2, t3);
                bl0[0] = t0; bl0[1] = t2; bl1[0] = t1; bl1[1] = t3;
                mma_bf16(o[2*p],   aph[s], bh0);
                mma_bf16(o[2*p],   aph[s], bl0);
                mma_bf16(o[2*p],   apl[s], bh0);
                mma_bf16(o[2*p+1], aph[s], bh1);
                mma_bf16(o[2*p+1], aph[s], bl1);
                mma_bf16(o[2*p+1], apl[s], bh1);
            }
        }

        __syncthreads();
        if (it + 2 < 16) load_stage(it + 2, it & 1);
        CP_COMMIT();
    }

    // epilogue
    float inv0 = 1.0f / l0, inv1 = 1.0f / l1;
    int r = lane >> 2;
    int row0 = q0 + wq * 16 + r;
    size_t base0 = ((size_t)(b * N_) + row0) * E_ + h * 64 + (lane & 3) * 2;
    size_t base1 = base0 + (size_t)8 * E_;
    #pragma unroll
    for (int t = 0; t < 8; t++) {
        float2 v0 = {o[t][0] * inv0, o[t][1] * inv0};
        float2 v1 = {o[t][2] * inv1, o[t][3] * inv1};
        *(float2*)&O[base0 + t * 8] = v0;
        *(float2*)&O[base1 + t * 8] = v1;
    }
}

// ---------------------------------------------------------------------------
extern "C" void kernel_launch(void* const* d_in, const int* in_sizes, int n_in,
                              void* d_out, int out_size)
{
    (void)in_sizes; (void)n_in; (void)out_size;
    const float* x      = (const float*)d_in[0];
    const float* w_qkv  = (const float*)d_in[1];
    const float* b_qkv  = (const float*)d_in[2];
    const float* w_proj = (const float*)d_in[3];
    const float* b_proj = (const float*)d_in[4];
    float* out = (float*)d_out;

    float *qkv, *ao;
    __nv_bfloat16 *xh, *xl, *wqh, *wql, *wph, *wpl, *aoh, *aol;
    __nv_bfloat16 *qh2, *ql2, *kh2, *kl2, *vth, *vtl;
    cudaGetSymbolAddress((void**)&qkv, g_qkv);
    cudaGetSymbolAddress((void**)&ao,  g_ao);
    cudaGetSymbolAddress((void**)&xh,  g_xh);
    cudaGetSymbolAddress((void**)&xl,  g_xl);
    cudaGetSymbolAddress((void**)&wqh, g_wqh);
    cudaGetSymbolAddress((void**)&wql, g_wql);
    cudaGetSymbolAddress((void**)&wph, g_wph);
    cudaGetSymbolAddress((void**)&wpl, g_wpl);
    cudaGetSymbolAddress((void**)&aoh, g_aoh);
    cudaGetSymbolAddress((void**)&aol, g_aol);
    cudaGetSymbolAddress((void**)&qh2, g_qh2);
    cudaGetSymbolAddress((void**)&ql2, g_ql2);
    cudaGetSymbolAddress((void**)&kh2, g_kh2);
    cudaGetSymbolAddress((void**)&kl2, g_kl2);
    cudaGetSymbolAddress((void**)&vth, g_vth);
    cudaGetSymbolAddress((void**)&vtl, g_vtl);

    const int GEMM_SMEM = 2 * 32768;
    cudaFuncSetAttribute(tc_gemm, cudaFuncAttributeMaxDynamicSharedMemorySize, GEMM_SMEM);
    const int ATTN_SMEM = 32768 + 2 * 32768;
    cudaFuncSetAttribute(attn_mma, cudaFuncAttributeMaxDynamicSharedMemorySize, ATTN_SMEM);

    // 1) split-convert x
    {
        int n4 = M_ * E_ / 4;
        convert_split<<<(n4 + 255) / 256, 256>>>((const float4*)x, (uint2*)xh, (uint2*)xl, n4);
    }
    // 2) transpose+split weights
    {
        dim3 blk(32, 8);
        convert_w_t<<<dim3(3 * E_ / 32, E_ / 32), blk>>>(w_qkv, wqh, wql, E_, 3 * E_);
        convert_w_t<<<dim3(E_ / 32, E_ / 32), blk>>>(w_proj, wph, wpl, E_, E_);
    }
    // 3) QKV GEMM
    {
        dim3 grid(3 * E_ / 128, M_ / 128);
        tc_gemm<<<grid, 256, GEMM_SMEM>>>(xh, xl, wqh, wql, b_qkv, qkv, M_, 3 * E_, E_);
    }
    // 4) RoPE + split + V transpose
    {
        dim3 grid(N_ / 128, B_ * H_);
        rope_split_v2<<<grid, 256>>>(qkv, qh2, ql2, kh2, kl2, vth, vtl);
    }
    // 5) Tensor-core flash attention
    {
        dim3 grid(N_ / 128, B_ * H_);
        attn_mma<<<grid, 256, ATTN_SMEM>>>(qh2, ql2, kh2, kl2, vth, vtl, ao);
    }
    // 6) split-convert attention output
    {
        int n4 = M_ * E_ / 4;
        convert_split<<<(n4 + 255) / 256, 256>>>((const float4*)ao, (uint2*)aoh, (uint2*)aol, n4);
    }
    // 7) projection GEMM
    {
        dim3 grid(E_ / 128, M_ / 128);
        tc_gemm<<<grid, 256, GEMM_SMEM>>>(aoh, aol, wph, wpl, b_proj, out, M_, E_, E_);
    }
}

// round 5
// speedup vs baseline: 2.6617x; 1.0473x over previous
#include <cuda_runtime.h>
#include <cuda_bf16.h>
#include <math.h>
#include <stdint.h>

#define B_ 8
#define N_ 1024
#define E_ 768
#define H_ 12
#define D_ 64
#define M_ (B_*N_)   // 8192

// ---------------------------------------------------------------------------
// Scratch (__device__ globals; no allocations allowed)
// ---------------------------------------------------------------------------
__device__ __nv_bfloat16 g_xh[(size_t)M_ * E_];
__device__ __nv_bfloat16 g_xl[(size_t)M_ * E_];
__device__ __nv_bfloat16 g_wqh[(size_t)3*E_ * E_];
__device__ __nv_bfloat16 g_wql[(size_t)3*E_ * E_];
__device__ __nv_bfloat16 g_wph[(size_t)E_ * E_];
__device__ __nv_bfloat16 g_wpl[(size_t)E_ * E_];
__device__ __nv_bfloat16 g_aoh[(size_t)M_ * E_];
__device__ __nv_bfloat16 g_aol[(size_t)M_ * E_];
__device__ __nv_bfloat16 g_qh2[(size_t)B_*H_*N_*D_];
__device__ __nv_bfloat16 g_ql2[(size_t)B_*H_*N_*D_];
__device__ __nv_bfloat16 g_kh2[(size_t)B_*H_*N_*D_];
__device__ __nv_bfloat16 g_kl2[(size_t)B_*H_*N_*D_];
__device__ __nv_bfloat16 g_vth[(size_t)B_*H_*D_*N_];
__device__ __nv_bfloat16 g_vtl[(size_t)B_*H_*D_*N_];

// ---------------------------------------------------------------------------
// PTX helpers
// ---------------------------------------------------------------------------
__device__ __forceinline__ uint32_t smem_u32(const void* p) {
    uint32_t a;
    asm("{ .reg .u64 t; cvta.to.shared.u64 t, %1; cvt.u32.u64 %0, t; }" : "=r"(a) : "l"(p));
    return a;
}
#define CPA16(dst, src) \
    asm volatile("cp.async.cg.shared.global [%0], [%1], 16;" :: "r"(dst), "l"(src) : "memory")
#define CP_COMMIT() asm volatile("cp.async.commit_group;" ::: "memory")
#define CP_WAIT1()  asm volatile("cp.async.wait_group 1;" ::: "memory")
#define CP_WAIT2()  asm volatile("cp.async.wait_group 2;" ::: "memory")

__device__ __forceinline__ void ldsm_x4(uint32_t addr, uint32_t& r0, uint32_t& r1,
                                        uint32_t& r2, uint32_t& r3) {
    asm volatile("ldmatrix.sync.aligned.m8n8.x4.shared.b16 {%0,%1,%2,%3}, [%4];"
                 : "=r"(r0), "=r"(r1), "=r"(r2), "=r"(r3) : "r"(addr));
}
__device__ __forceinline__ void mma_bf16(float* c, const uint32_t* a, const uint32_t* b) {
    asm volatile("mma.sync.aligned.m16n8k16.row.col.f32.bf16.bf16.f32 "
        "{%0,%1,%2,%3}, {%4,%5,%6,%7}, {%8,%9}, {%0,%1,%2,%3};"
        : "+f"(c[0]), "+f"(c[1]), "+f"(c[2]), "+f"(c[3])
        : "r"(a[0]), "r"(a[1]), "r"(a[2]), "r"(a[3]), "r"(b[0]), "r"(b[1]));
}
__device__ __forceinline__ uint32_t pack_bf16x2(float lo, float hi) {
    __nv_bfloat162 t = __floats2bfloat162_rn(lo, hi);
    return *(uint32_t*)&t;
}
// split two fp32 into packed hi-bf16x2 and lo-bf16x2
__device__ __forceinline__ void split2(float v0, float v1, uint32_t& hi, uint32_t& lo) {
    __nv_bfloat16 h0 = __float2bfloat16(v0), h1 = __float2bfloat16(v1);
    hi = (uint32_t)__bfloat16_as_ushort(h0) | ((uint32_t)__bfloat16_as_ushort(h1) << 16);
    lo = pack_bf16x2(v0 - __bfloat162float(h0), v1 - __bfloat162float(h1));
}

// ---------------------------------------------------------------------------
// convert: fp32 -> (hi, lo) bf16
// ---------------------------------------------------------------------------
__global__ void convert_split(const float4* __restrict__ in,
                              uint2* __restrict__ hi, uint2* __restrict__ lo, int n4)
{
    int i = blockIdx.x * blockDim.x + threadIdx.x;
    if (i >= n4) return;
    float4 v = in[i];
    uint2 H, L;
    split2(v.x, v.y, H.x, L.x);
    split2(v.z, v.w, H.y, L.y);
    hi[i] = H;
    lo[i] = L;
}

__global__ void convert_w_t(const float* __restrict__ W,
                            __nv_bfloat16* __restrict__ Th, __nv_bfloat16* __restrict__ Tl,
                            int K, int N)
{
    __shared__ float tile[32][33];
    int n0 = blockIdx.x * 32, k0 = blockIdx.y * 32;
    int tx = threadIdx.x, ty = threadIdx.y;
    for (int i = ty; i < 32; i += 8)
        tile[i][tx] = W[(size_t)(k0 + i) * N + n0 + tx];
    __syncthreads();
    for (int i = ty; i < 32; i += 8) {
        float v = tile[tx][i];
        __nv_bfloat16 h = __float2bfloat16(v);
        Th[(size_t)(n0 + i) * K + k0 + tx] = h;
        Tl[(size_t)(n0 + i) * K + k0 + tx] = __float2bfloat16(v - __bfloat162float(h));
    }
}

// ---------------------------------------------------------------------------
// Shared GEMM mainloop: acc[2][8][4] += A[M,K] @ B^T[N,K], split-bf16 3-term.
// 128x128 block, BK=32, 3-stage cp.async (stage stride 32KB), 8 warps.
// Term-reordered MMAs (no back-to-back accumulator reuse).
// ---------------------------------------------------------------------------
__device__ __forceinline__ void gemm_mainloop(
    uint32_t sbase, int tid, int lane, int wm, int wn,
    const __nv_bfloat16* __restrict__ Ah, const __nv_bfloat16* __restrict__ Al,
    const __nv_bfloat16* __restrict__ Bh, const __nv_bfloat16* __restrict__ Bl,
    int m0, int n0, int Ktot, float (&acc)[2][8][4])
{
    const int NCH = Ktot / 32;

    auto load_stage = [&](int ch, int st) {
        uint32_t sb = sbase + (uint32_t)st * 32768u;
        int kb = ch * 32;
        #pragma unroll
        for (int u = 0; u < 2; u++) {
            int idx = tid + u * 256;
            int row = idx >> 2, chunk = idx & 3;
            uint32_t soff = (uint32_t)(row * 64 + ((chunk ^ (row & 3)) * 16));
            size_t ga = (size_t)(m0 + row) * Ktot + kb + chunk * 8;
            size_t gb = (size_t)(n0 + row) * Ktot + kb + chunk * 8;
            CPA16(sb +         soff, (const void*)(Ah + ga));
            CPA16(sb + 8192u + soff, (const void*)(Al + ga));
            CPA16(sb + 16384u + soff, (const void*)(Bh + gb));
            CPA16(sb + 24576u + soff, (const void*)(Bl + gb));
        }
    };

    auto compute_stage = [&](int st) {
        uint32_t sA  = sbase + (uint32_t)st * 32768u;
        uint32_t sAl = sA + 8192u;
        uint32_t sB  = sA + 16384u;
        uint32_t sBl = sA + 24576u;
        #pragma unroll
        for (int ks = 0; ks < 2; ks++) {
            uint32_t ah[2][4], al[2][4];
            #pragma unroll
            for (int mi = 0; mi < 2; mi++) {
                int r = wm * 32 + mi * 16 + (lane & 15);
                int chunk = ks * 2 + (lane >> 4);
                uint32_t off = (uint32_t)(r * 64 + ((chunk ^ (r & 3)) * 16));
                ldsm_x4(sA  + off, ah[mi][0], ah[mi][1], ah[mi][2], ah[mi][3]);
                ldsm_x4(sAl + off, al[mi][0], al[mi][1], al[mi][2], al[mi][3]);
            }
            uint32_t bh[8][2], bl[8][2];
            #pragma unroll
            for (int p = 0; p < 4; p++) {
                int r = wn * 64 + p * 16 + (lane & 15);
                int chunk = ks * 2 + (lane >> 4);
                uint32_t off = (uint32_t)(r * 64 + ((chunk ^ (r & 3)) * 16));
                uint32_t t0, t1, t2, t3;
                ldsm_x4(sB + off, t0, t1, t2, t3);
                bh[2*p][0] = t0; bh[2*p][1] = t2; bh[2*p+1][0] = t1; bh[2*p+1][1] = t3;
                ldsm_x4(sBl + off, t0, t1, t2, t3);
                bl[2*p][0] = t0; bl[2*p][1] = t2; bl[2*p+1][0] = t1; bl[2*p+1][1] = t3;
            }
            // term-reordered: consecutive MMAs hit distinct accumulators
            #pragma unroll
            for (int mi = 0; mi < 2; mi++)
                #pragma unroll
                for (int ni = 0; ni < 8; ni++)
                    mma_bf16(acc[mi][ni], ah[mi], bh[ni]);
            #pragma unroll
            for (int mi = 0; mi < 2; mi++)
                #pragma unroll
                for (int ni = 0; ni < 8; ni++)
                    mma_bf16(acc[mi][ni], ah[mi], bl[ni]);
            #pragma unroll
            for (int mi = 0; mi < 2; mi++)
                #pragma unroll
                for (int ni = 0; ni < 8; ni++)
                    mma_bf16(acc[mi][ni], al[mi], bh[ni]);
        }
    };

    load_stage(0, 0); CP_COMMIT();
    load_stage(1, 1); CP_COMMIT();
    load_stage(2, 2); CP_COMMIT();

    int st = 0;
    for (int ch = 0; ch < NCH; ch++) {
        CP_WAIT2();
        __syncthreads();
        compute_stage(st);
        __syncthreads();
        if (ch + 3 < NCH) load_stage(ch + 3, st);
        CP_COMMIT();
        st = (st == 2) ? 0 : st + 1;
    }
}

// ---------------------------------------------------------------------------
// Fused QKV GEMM: bias + RoPE + hi/lo split + V-transpose, all in epilogue.
// Output section per N-tile: n0<768 Q, <1536 K, else V (tiles never straddle).
// ---------------------------------------------------------------------------
__global__ __launch_bounds__(256, 2)
void tc_gemm_qkv(const __nv_bfloat16* __restrict__ Ah, const __nv_bfloat16* __restrict__ Al,
                 const __nv_bfloat16* __restrict__ Bh, const __nv_bfloat16* __restrict__ Bl,
                 const float* __restrict__ bias,
                 __nv_bfloat16* __restrict__ Qh, __nv_bfloat16* __restrict__ Ql,
                 __nv_bfloat16* __restrict__ Kh, __nv_bfloat16* __restrict__ Kl,
                 __nv_bfloat16* __restrict__ Vth, __nv_bfloat16* __restrict__ Vtl)
{
    extern __shared__ char smem[];
    uint32_t sbase = smem_u32(smem);
    int tid = threadIdx.x, lane = tid & 31, wid = tid >> 5;
    int wm = wid & 3, wn = wid >> 2;
    int m0 = blockIdx.y * 128, n0 = blockIdx.x * 128;

    float acc[2][8][4];
    #pragma unroll
    for (int mi = 0; mi < 2; mi++)
        #pragma unroll
        for (int ni = 0; ni < 8; ni++)
            #pragma unroll
            for (int e = 0; e < 4; e++) acc[mi][ni][e] = 0.f;

    gemm_mainloop(sbase, tid, lane, wm, wn, Ah, Al, Bh, Bl, m0, n0, E_, acc);

    // bias
    #pragma unroll
    for (int ni = 0; ni < 8; ni++) {
        int col = n0 + wn * 64 + ni * 8 + (lane & 3) * 2;
        float2 bv = *(const float2*)&bias[col];
        #pragma unroll
        for (int mi = 0; mi < 2; mi++) {
            acc[mi][ni][0] += bv.x; acc[mi][ni][1] += bv.y;
            acc[mi][ni][2] += bv.x; acc[mi][ni][3] += bv.y;
        }
    }

    int sec = n0 / 768;
    int nsec = n0 - sec * 768;
    int b = m0 >> 10;
    int t_base = m0 & 1023;

    if (sec < 2) {
        // ---- Q or K: RoPE in registers, split, write [bh][t][64] ----
        int h = nsec / 64 + wn;
        int bh = b * H_ + h;
        float cs[8], sn[8];
        #pragma unroll
        for (int u = 0; u < 8; u++) {
            int d2 = (u >> 1) * 8 + (lane & 3) * 2 + (u & 1);
            float f = (float)h * exp2f(-(float)d2 * (13.287712379549449f / 32.0f));
            sincosf(f, &sn[u], &cs[u]);
        }
        __nv_bfloat16* Oh = (sec == 0) ? Qh : Kh;
        __nv_bfloat16* Ol = (sec == 0) ? Ql : Kl;
        const float scale = (sec == 0) ? 0.125f : 1.0f;

        #pragma unroll
        for (int mi = 0; mi < 2; mi++) {
            int rbase = wm * 32 + mi * 16 + (lane >> 2);
            #pragma unroll
            for (int eh = 0; eh < 2; eh++) {
                int t = t_base + rbase + eh * 8;
                size_t rowoff = ((size_t)bh * N_ + t) * (size_t)D_;
                #pragma unroll
                for (int ni = 0; ni < 4; ni++) {
                    float a0 = acc[mi][ni][eh*2+0], b0 = acc[mi][ni+4][eh*2+0];
                    float a1 = acc[mi][ni][eh*2+1], b1 = acc[mi][ni+4][eh*2+1];
                    int u0 = ni * 2, u1 = u0 + 1;
                    float lo0 = (a0 * cs[u0] - b0 * sn[u0]) * scale;
                    float hi0 = (b0 * cs[u0] + a0 * sn[u0]) * scale;
                    float lo1 = (a1 * cs[u1] - b1 * sn[u1]) * scale;
                    float hi1 = (b1 * cs[u1] + a1 * sn[u1]) * scale;
                    int d0 = ni * 8 + (lane & 3) * 2;
                    uint32_t H, L;
                    split2(lo0, lo1, H, L);
                    *(uint32_t*)(Oh + rowoff + d0) = H;
                    *(uint32_t*)(Ol + rowoff + d0) = L;
                    split2(hi0, hi1, H, L);
                    *(uint32_t*)(Oh + rowoff + d0 + 32) = H;
                    *(uint32_t*)(Ol + rowoff + d0 + 32) = L;
                }
            }
        }
    } else {
        // ---- V: transpose via smem, split, write [bh][d][t] ----
        float* sv = (float*)smem;   // [128 cols][stride 129]
        #pragma unroll
        for (int mi = 0; mi < 2; mi++)
            #pragma unroll
            for (int ni = 0; ni < 8; ni++)
                #pragma unroll
                for (int e = 0; e < 4; e++) {
                    int col = wn * 64 + ni * 8 + (lane & 3) * 2 + (e & 1);
                    int r = wm * 32 + mi * 16 + (lane >> 2) + ((e >> 1) * 8);
                    sv[col * 129 + r] = acc[mi][ni][e];
                }
        __syncthreads();
        for (int i = tid; i < 128 * 32; i += 256) {
            int col = i >> 5, t4 = (i & 31) * 4;
            float v0 = sv[col * 129 + t4 + 0];
            float v1 = sv[col * 129 + t4 + 1];
            float v2 = sv[col * 129 + t4 + 2];
            float v3 = sv[col * 129 + t4 + 3];
            int hv = nsec / 64 + (col >> 6);
            int d = col & 63;
            int bhv = b * H_ + hv;
            size_t ob = ((size_t)bhv * D_ + d) * (size_t)N_ + t_base + t4;
            uint2 Hv, Lv;
            split2(v0, v1, Hv.x, Lv.x);
            split2(v2, v3, Hv.y, Lv.y);
            *(uint2*)(Vth + ob) = Hv;
            *(uint2*)(Vtl + ob) = Lv;
        }
    }
}

// ---------------------------------------------------------------------------
// Plain GEMM (projection): fp32 out + bias.
// ---------------------------------------------------------------------------
__global__ __launch_bounds__(256, 2)
void tc_gemm(const __nv_bfloat16* __restrict__ Ah, const __nv_bfloat16* __restrict__ Al,
             const __nv_bfloat16* __restrict__ Bh, const __nv_bfloat16* __restrict__ Bl,
             const float* __restrict__ bias, float* __restrict__ C,
             int Ntot, int Ktot)
{
    extern __shared__ char smem[];
    uint32_t sbase = smem_u32(smem);
    int tid = threadIdx.x, lane = tid & 31, wid = tid >> 5;
    int wm = wid & 3, wn = wid >> 2;
    int m0 = blockIdx.y * 128, n0 = blockIdx.x * 128;

    float acc[2][8][4];
    #pragma unroll
    for (int mi = 0; mi < 2; mi++)
        #pragma unroll
        for (int ni = 0; ni < 8; ni++)
            #pragma unroll
            for (int e = 0; e < 4; e++) acc[mi][ni][e] = 0.f;

    gemm_mainloop(sbase, tid, lane, wm, wn, Ah, Al, Bh, Bl, m0, n0, Ktot, acc);

    #pragma unroll
    for (int mi = 0; mi < 2; mi++) {
        #pragma unroll
        for (int ni = 0; ni < 8; ni++) {
            int row = m0 + wm * 32 + mi * 16 + (lane >> 2);
            int col = n0 + wn * 64 + ni * 8 + (lane & 3) * 2;
            float2 bv = *(const float2*)&bias[col];
            float2 v0 = {acc[mi][ni][0] + bv.x, acc[mi][ni][1] + bv.y};
            float2 v1 = {acc[mi][ni][2] + bv.x, acc[mi][ni][3] + bv.y};
            *(float2*)&C[(size_t)row * Ntot + col] = v0;
            *(float2*)&C[(size_t)(row + 8) * Ntot + col] = v1;
        }
    }
}

// ---------------------------------------------------------------------------
// Tensor-core flash attention (as R4, + term reorder + bf16 split epilogue).
// ---------------------------------------------------------------------------
__global__ __launch_bounds__(256, 2) void attn_mma(
    const __nv_bfloat16* __restrict__ Qh, const __nv_bfloat16* __restrict__ Ql,
    const __nv_bfloat16* __restrict__ Kh, const __nv_bfloat16* __restrict__ Kl,
    const __nv_bfloat16* __restrict__ Vth, const __nv_bfloat16* __restrict__ Vtl,
    __nv_bfloat16* __restrict__ Oh, __nv_bfloat16* __restrict__ Ol)
{
    extern __shared__ char smem[];
    uint32_t sb = smem_u32(smem);
    const uint32_t oQh = 0, oQl = 16384, oStage = 32768;

    int tid = threadIdx.x, lane = tid & 31, wq = tid >> 5;
    int bh = blockIdx.y;
    int q0 = blockIdx.x * 128;
    int b = bh / H_, h = bh % H_;

    const __nv_bfloat16* Qhb = Qh + ((size_t)bh * N_ + q0) * D_;
    const __nv_bfloat16* Qlb = Ql + ((size_t)bh * N_ + q0) * D_;
    const __nv_bfloat16* Khb = Kh + (size_t)bh * N_ * D_;
    const __nv_bfloat16* Klb = Kl + (size_t)bh * N_ * D_;
    const __nv_bfloat16* Vhb = Vth + (size_t)bh * D_ * N_;
    const __nv_bfloat16* Vlb = Vtl + (size_t)bh * D_ * N_;

    for (int u = tid; u < 2048; u += 256) {
        int split = u >> 10;
        int idx = u & 1023;
        int r = idx >> 3, chunk = idx & 7;
        uint32_t off = (uint32_t)(r * 128 + ((chunk ^ (r & 7)) * 16));
        const __nv_bfloat16* src = (split ? Qlb : Qhb) + (size_t)r * D_ + chunk * 8;
        CPA16(sb + (split ? oQl : oQh) + off, (const void*)src);
    }

    auto load_stage = [&](int it, int st) {
        int jt = it * 64;
        uint32_t s0 = sb + oStage + (uint32_t)st * 32768u;
        for (int u = tid; u < 2048; u += 256) {
            int part = u >> 9;
            int idx = u & 511;
            int r = idx >> 3, chunk = idx & 7;
            uint32_t off = (uint32_t)(r * 128 + ((chunk ^ (r & 7)) * 16));
            const __nv_bfloat16* src;
            if (part == 0)      src = Khb + (size_t)(jt + r) * D_ + chunk * 8;
            else if (part == 1) src = Klb + (size_t)(jt + r) * D_ + chunk * 8;
            else if (part == 2) src = Vhb + (size_t)r * N_ + jt + chunk * 8;
            else                src = Vlb + (size_t)r * N_ + jt + chunk * 8;
            CPA16(s0 + (uint32_t)part * 8192u + off, (const void*)src);
        }
    };

    float o[8][4];
    #pragma unroll
    for (int i = 0; i < 8; i++)
        #pragma unroll
        for (int j = 0; j < 4; j++) o[i][j] = 0.f;
    float m0v = -1e30f, m1v = -1e30f, l0 = 0.f, l1 = 0.f;

    load_stage(0, 0); CP_COMMIT();
    load_stage(1, 1); CP_COMMIT();

    for (int it = 0; it < 16; it++) {
        CP_WAIT1();
        __syncthreads();
        uint32_t sK = sb + oStage + (uint32_t)(it & 1) * 32768u;

        float c[8][4];
        #pragma unroll
        for (int i = 0; i < 8; i++)
            #pragma unroll
            for (int j = 0; j < 4; j++) c[i][j] = 0.f;

        #pragma unroll
        for (int ks = 0; ks < 4; ks++) {
            int chunk = ks * 2 + (lane >> 4);
            int rq = wq * 16 + (lane & 15);
            uint32_t offq = (uint32_t)(rq * 128 + ((chunk ^ (rq & 7)) * 16));
            uint32_t ah[4], al[4];
            ldsm_x4(sb + oQh + offq, ah[0], ah[1], ah[2], ah[3]);
            ldsm_x4(sb + oQl + offq, al[0], al[1], al[2], al[3]);
            uint32_t bh_[8][2], bl_[8][2];
            #pragma unroll
            for (int p = 0; p < 4; p++) {
                int rk = p * 16 + (lane & 15);
                uint32_t offk = (uint32_t)(rk * 128 + ((chunk ^ (rk & 7)) * 16));
                uint32_t t0, t1, t2, t3;
                ldsm_x4(sK + offk, t0, t1, t2, t3);
                bh_[2*p][0] = t0; bh_[2*p][1] = t2; bh_[2*p+1][0] = t1; bh_[2*p+1][1] = t3;
                ldsm_x4(sK + 8192u + offk, t0, t1, t2, t3);
                bl_[2*p][0] = t0; bl_[2*p][1] = t2; bl_[2*p+1][0] = t1; bl_[2*p+1][1] = t3;
            }
            #pragma unroll
            for (int nt = 0; nt < 8; nt++) mma_bf16(c[nt], ah, bh_[nt]);
            #pragma unroll
            for (int nt = 0; nt < 8; nt++) mma_bf16(c[nt], ah, bl_[nt]);
            #pragma unroll
            for (int nt = 0; nt < 8; nt++) mma_bf16(c[nt], al, bh_[nt]);
        }

        // online softmax
        {
            float mt0 = -1e30f, mt1 = -1e30f;
            #pragma unroll
            for (int t = 0; t < 8; t++) {
                mt0 = fmaxf(mt0, fmaxf(c[t][0], c[t][1]));
                mt1 = fmaxf(mt1, fmaxf(c[t][2], c[t][3]));
            }
            mt0 = fmaxf(mt0, __shfl_xor_sync(0xffffffffu, mt0, 1));
            mt0 = fmaxf(mt0, __shfl_xor_sync(0xffffffffu, mt0, 2));
            mt1 = fmaxf(mt1, __shfl_xor_sync(0xffffffffu, mt1, 1));
            mt1 = fmaxf(mt1, __shfl_xor_sync(0xffffffffu, mt1, 2));
            float mn0 = fmaxf(m0v, mt0), mn1 = fmaxf(m1v, mt1);
            float f0 = __expf(m0v - mn0), f1 = __expf(m1v - mn1);
            m0v = mn0; m1v = mn1;
            float ps0 = 0.f, ps1 = 0.f;
            #pragma unroll
            for (int t = 0; t < 8; t++) {
                c[t][0] = __expf(c[t][0] - mn0); ps0 += c[t][0];
                c[t][1] = __expf(c[t][1] - mn0); ps0 += c[t][1];
                c[t][2] = __expf(c[t][2] - mn1); ps1 += c[t][2];
                c[t][3] = __expf(c[t][3] - mn1); ps1 += c[t][3];
            }
            ps0 += __shfl_xor_sync(0xffffffffu, ps0, 1);
            ps0 += __shfl_xor_sync(0xffffffffu, ps0, 2);
            ps1 += __shfl_xor_sync(0xffffffffu, ps1, 1);
            ps1 += __shfl_xor_sync(0xffffffffu, ps1, 2);
            l0 = l0 * f0 + ps0;
            l1 = l1 * f1 + ps1;
            #pragma unroll
            for (int t = 0; t < 8; t++) {
                o[t][0] *= f0; o[t][1] *= f0;
                o[t][2] *= f1; o[t][3] *= f1;
            }
        }

        // P fragments (hi/lo)
        uint32_t aph[4][4], apl[4][4];
        #pragma unroll
        for (int s = 0; s < 4; s++) {
            #pragma unroll
            for (int half = 0; half < 2; half++) {
                int t = 2 * s + half;
                split2(c[t][0], c[t][1], aph[s][half*2+0], apl[s][half*2+0]);
                split2(c[t][2], c[t][3], aph[s][half*2+1], apl[s][half*2+1]);
            }
        }

        // O += P V
        #pragma unroll
        for (int s = 0; s < 4; s++) {
            int chunk = s * 2 + (lane >> 4);
            uint32_t bh_[8][2], bl_[8][2];
            #pragma unroll
            for (int p = 0; p < 4; p++) {
                int rd = p * 16 + (lane & 15);
                uint32_t off = (uint32_t)(rd * 128 + ((chunk ^ (rd & 7)) * 16));
                uint32_t t0, t1, t2, t3;
                ldsm_x4(sK + 16384u + off, t0, t1, t2, t3);
                bh_[2*p][0] = t0; bh_[2*p][1] = t2; bh_[2*p+1][0] = t1; bh_[2*p+1][1] = t3;
                ldsm_x4(sK + 24576u + off, t0, t1, t2, t3);
                bl_[2*p][0] = t0; bl_[2*p][1] = t2; bl_[2*p+1][0] = t1; bl_[2*p+1][1] = t3;
            }
            #pragma unroll
            for (int nt = 0; nt < 8; nt++) mma_bf16(o[nt], aph[s], bh_[nt]);
            #pragma unroll
            for (int nt = 0; nt < 8; nt++) mma_bf16(o[nt], aph[s], bl_[nt]);
            #pragma unroll
            for (int nt = 0; nt < 8; nt++) mma_bf16(o[nt], apl[s], bh_[nt]);
        }

        __syncthreads();
        if (it + 2 < 16) load_stage(it + 2, it & 1);
        CP_COMMIT();
    }

    // epilogue: normalize + hi/lo split directly to bf16 operand buffers
    float inv0 = 1.0f / l0, inv1 = 1.0f / l1;
    int r = lane >> 2;
    int row0 = q0 + wq * 16 + r;
    size_t base0 = ((size_t)(b * N_) + row0) * E_ + h * 64 + (lane & 3) * 2;
    size_t base1 = base0 + (size_t)8 * E_;
    #pragma unroll
    for (int t = 0; t < 8; t++) {
        uint32_t H, L;
        split2(o[t][0] * inv0, o[t][1] * inv0, H, L);
        *(uint32_t*)(Oh + base0 + t * 8) = H;
        *(uint32_t*)(Ol + base0 + t * 8) = L;
        split2(o[t][2] * inv1, o[t][3] * inv1, H, L);
        *(uint32_t*)(Oh + base1 + t * 8) = H;
        *(uint32_t*)(Ol + base1 + t * 8) = L;
    }
}

// ---------------------------------------------------------------------------
extern "C" void kernel_launch(void* const* d_in, const int* in_sizes, int n_in,
                              void* d_out, int out_size)
{
    (void)in_sizes; (void)n_in; (void)out_size;
    const float* x      = (const float*)d_in[0];
    const float* w_qkv  = (const float*)d_in[1];
    const float* b_qkv  = (const float*)d_in[2];
    const float* w_proj = (const float*)d_in[3];
    const float* b_proj = (const float*)d_in[4];
    float* out = (float*)d_out;

    __nv_bfloat16 *xh, *xl, *wqh, *wql, *wph, *wpl, *aoh, *aol;
    __nv_bfloat16 *qh2, *ql2, *kh2, *kl2, *vth, *vtl;
    cudaGetSymbolAddress((void**)&xh,  g_xh);
    cudaGetSymbolAddress((void**)&xl,  g_xl);
    cudaGetSymbolAddress((void**)&wqh, g_wqh);
    cudaGetSymbolAddress((void**)&wql, g_wql);
    cudaGetSymbolAddress((void**)&wph, g_wph);
    cudaGetSymbolAddress((void**)&wpl, g_wpl);
    cudaGetSymbolAddress((void**)&aoh, g_aoh);
    cudaGetSymbolAddress((void**)&aol, g_aol);
    cudaGetSymbolAddress((void**)&qh2, g_qh2);
    cudaGetSymbolAddress((void**)&ql2, g_ql2);
    cudaGetSymbolAddress((void**)&kh2, g_kh2);
    cudaGetSymbolAddress((void**)&kl2, g_kl2);
    cudaGetSymbolAddress((void**)&vth, g_vth);
    cudaGetSymbolAddress((void**)&vtl, g_vtl);

    const int GEMM_SMEM = 3 * 32768;   // 96KB, 3 stages
    cudaFuncSetAttribute(tc_gemm_qkv, cudaFuncAttributeMaxDynamicSharedMemorySize, GEMM_SMEM);
    cudaFuncSetAttribute(tc_gemm, cudaFuncAttributeMaxDynamicSharedMemorySize, GEMM_SMEM);
    const int ATTN_SMEM = 32768 + 2 * 32768;
    cudaFuncSetAttribute(attn_mma, cudaFuncAttributeMaxDynamicSharedMemorySize, ATTN_SMEM);

    // 1) split-convert x
    {
        int n4 = M_ * E_ / 4;
        convert_split<<<(n4 + 255) / 256, 256>>>((const float4*)x, (uint2*)xh, (uint2*)xl, n4);
    }
    // 2) transpose+split weights
    {
        dim3 blk(32, 8);
        convert_w_t<<<dim3(3 * E_ / 32, E_ / 32), blk>>>(w_qkv, wqh, wql, E_, 3 * E_);
        convert_w_t<<<dim3(E_ / 32, E_ / 32), blk>>>(w_proj, wph, wpl, E_, E_);
    }
    // 3) fused QKV GEMM + bias + RoPE + split + V transpose
    {
        dim3 grid(3 * E_ / 128, M_ / 128);
        tc_gemm_qkv<<<grid, 256, GEMM_SMEM>>>(xh, xl, wqh, wql, b_qkv,
                                              qh2, ql2, kh2, kl2, vth, vtl);
    }
    // 4) tensor-core flash attention (writes split bf16 directly)
    {
        dim3 grid(N_ / 128, B_ * H_);
        attn_mma<<<grid, 256, ATTN_SMEM>>>(qh2, ql2, kh2, kl2, vth, vtl, aoh, aol);
    }
    // 5) projection GEMM
    {
        dim3 grid(E_ / 128, M_ / 128);
        tc_gemm<<<grid, 256, GEMM_SMEM>>>(aoh, aol, wph, wpl, b_proj, out, E_, E_);
    }
}